// round 12
// baseline (speedup 1.0000x reference)
#include <cuda_runtime.h>
#include <cuda_bf16.h>
#include <mma.h>
#include <cstdint>
#include <cstddef>

using namespace nvcuda;

#define T_SEQ 1024
#define B_SZ  64
// E = 256, H = 256, 4H = 1024

// ---------------- device-global scratch (no allocations) ----------------
__device__ float g_x   [(size_t)B_SZ * T_SEQ * 256];   // gathered embeddings
__device__ float g_xw1f[(size_t)B_SZ * T_SEQ * 1024];  // x @ fw1_Wi
__device__ float g_xw1b[(size_t)B_SZ * T_SEQ * 1024];  // x @ bw1_Wi
__device__ float g_xw2 [(size_t)B_SZ * T_SEQ * 1024];  // x1 @ fw2_Wi
__device__ float g_x1  [(size_t)B_SZ * T_SEQ * 512];   // layer-1 output [fwd|bwd]
__device__ float g_h2f [B_SZ * 256];                   // layer-2 fwd final h
__device__ __nv_bfloat16 g_hb[3][2][B_SZ * 256];       // h double buffers (l1f, l1b, l2)
__device__ unsigned g_ctrs[32];                        // group barrier counters

// ---------------- helpers ----------------
__device__ __forceinline__ float tanh_ap(float x) {
    float y;
    asm("tanh.approx.f32 %0, %1;" : "=f"(y) : "f"(x));
    return y;
}
__device__ __forceinline__ float sig_ap(float x) {
    return fmaf(tanh_ap(0.5f * x), 0.5f, 0.5f);
}
__device__ __forceinline__ float sigf(float x) {
    return __fdividef(1.0f, 1.0f + __expf(-x));
}

// ---------------- init: zero barrier counters (every replay) ----------------
__global__ void init_kernel() {
    int i = threadIdx.x;
    if (i < 32) g_ctrs[i] = 0u;
}

// ---------------- embedding gather ----------------
__global__ void gather_kernel(const int* __restrict__ tok, const float* __restrict__ emb) {
    size_t idx = (size_t)blockIdx.x * blockDim.x + threadIdx.x;  // 65536*64 float4
    int row = (int)(idx >> 6);
    int f   = (int)(idx & 63);
    int t   = __ldg(&tok[row]);
    ((float4*)g_x)[idx] = __ldg(&((const float4*)emb)[(size_t)t * 64 + f]);
}

// ---------------- bf16 WMMA GEMM, double-buffered: C[M,N] = A[M,K] @ B[K,N] ----------------
#define GLDA 40
#define GLDB 136
__global__ __launch_bounds__(256, 2) void gemm_bf16(const float* __restrict__ A,
                                                    const float* __restrict__ B,
                                                    float* __restrict__ C,
                                                    int N, int K) {
    __shared__ __nv_bfloat16 As[2][128 * GLDA];
    __shared__ __nv_bfloat16 Bs[2][32 * GLDB];
    const int tid = threadIdx.x;
    const int w   = tid >> 5;
    const int m0  = blockIdx.y * 128;
    const int n0  = blockIdx.x * 128;
    const int wm0 = (w >> 2) * 64;
    const int wn0 = (w & 3) * 32;

    wmma::fragment<wmma::accumulator, 16, 16, 16, float> c[4][2];
    #pragma unroll
    for (int i = 0; i < 4; i++)
        #pragma unroll
        for (int j = 0; j < 2; j++) wmma::fill_fragment(c[i][j], 0.0f);

    float4 ra[4], rb[4];

    #pragma unroll
    for (int p = 0; p < 4; p++) {
        int idx = tid + p * 256;
        int row = idx >> 3, c4 = idx & 7;
        ra[p] = __ldg(&((const float4*)(A + (size_t)(m0 + row) * K))[c4]);
    }
    #pragma unroll
    for (int p = 0; p < 4; p++) {
        int idx = tid + p * 256;
        int row = idx >> 5, c4 = idx & 31;
        rb[p] = __ldg(&((const float4*)(B + (size_t)row * N + n0))[c4]);
    }
    #pragma unroll
    for (int p = 0; p < 4; p++) {
        int idx = tid + p * 256;
        int row = idx >> 3, c4 = idx & 7;
        __nv_bfloat162* dst = (__nv_bfloat162*)(&As[0][row * GLDA + c4 * 4]);
        dst[0] = __floats2bfloat162_rn(ra[p].x, ra[p].y);
        dst[1] = __floats2bfloat162_rn(ra[p].z, ra[p].w);
    }
    #pragma unroll
    for (int p = 0; p < 4; p++) {
        int idx = tid + p * 256;
        int row = idx >> 5, c4 = idx & 31;
        __nv_bfloat162* dst = (__nv_bfloat162*)(&Bs[0][row * GLDB + c4 * 4]);
        dst[0] = __floats2bfloat162_rn(rb[p].x, rb[p].y);
        dst[1] = __floats2bfloat162_rn(rb[p].z, rb[p].w);
    }
    __syncthreads();

    const int nkt = K >> 5;
    for (int kt = 0; kt < nkt; kt++) {
        const int cur = kt & 1;
        const bool more = (kt + 1 < nkt);
        if (more) {
            #pragma unroll
            for (int p = 0; p < 4; p++) {
                int idx = tid + p * 256;
                int row = idx >> 3, c4 = idx & 7;
                ra[p] = __ldg(&((const float4*)(A + (size_t)(m0 + row) * K + (kt + 1) * 32))[c4]);
            }
            #pragma unroll
            for (int p = 0; p < 4; p++) {
                int idx = tid + p * 256;
                int row = idx >> 5, c4 = idx & 31;
                rb[p] = __ldg(&((const float4*)(B + (size_t)((kt + 1) * 32 + row) * N + n0))[c4]);
            }
        }
        #pragma unroll
        for (int kk = 0; kk < 32; kk += 16) {
            wmma::fragment<wmma::matrix_a, 16, 16, 16, __nv_bfloat16, wmma::row_major> a[4];
            wmma::fragment<wmma::matrix_b, 16, 16, 16, __nv_bfloat16, wmma::row_major> b[2];
            #pragma unroll
            for (int i = 0; i < 4; i++)
                wmma::load_matrix_sync(a[i], &As[cur][(wm0 + i * 16) * GLDA + kk], GLDA);
            #pragma unroll
            for (int j = 0; j < 2; j++)
                wmma::load_matrix_sync(b[j], &Bs[cur][kk * GLDB + wn0 + j * 16], GLDB);
            #pragma unroll
            for (int i = 0; i < 4; i++)
                #pragma unroll
                for (int j = 0; j < 2; j++)
                    wmma::mma_sync(c[i][j], a[i], b[j], c[i][j]);
        }
        if (more) {
            const int nxt = cur ^ 1;
            #pragma unroll
            for (int p = 0; p < 4; p++) {
                int idx = tid + p * 256;
                int row = idx >> 3, c4 = idx & 7;
                __nv_bfloat162* dst = (__nv_bfloat162*)(&As[nxt][row * GLDA + c4 * 4]);
                dst[0] = __floats2bfloat162_rn(ra[p].x, ra[p].y);
                dst[1] = __floats2bfloat162_rn(ra[p].z, ra[p].w);
            }
            #pragma unroll
            for (int p = 0; p < 4; p++) {
                int idx = tid + p * 256;
                int row = idx >> 5, c4 = idx & 31;
                __nv_bfloat162* dst = (__nv_bfloat162*)(&Bs[nxt][row * GLDB + c4 * 4]);
                dst[0] = __floats2bfloat162_rn(rb[p].x, rb[p].y);
                dst[1] = __floats2bfloat162_rn(rb[p].z, rb[p].w);
            }
        }
        __syncthreads();
    }
    #pragma unroll
    for (int i = 0; i < 4; i++)
        #pragma unroll
        for (int j = 0; j < 2; j++)
            wmma::store_matrix_sync(C + (size_t)(m0 + wm0 + i * 16) * N + n0 + wn0 + j * 16,
                                    c[i][j], N, wmma::mem_row_major);
}

// ================= fused layer-1 scan: both directions per CTA =================
// Grid: 128 CTAs (1/SM), 256 threads. CTA (bg, ng): batch rows bg*8..+8,
// h-cols ng*16..+16, BOTH dirs. Per-bg group of 16 CTAs shares ONE counter.
// SMEM: Whs[2][256][72] bf16 | hs[2][16][264] bf16 | zb[2][2][16][68] f32
#define F_WHS_LD 72
#define F_HS_LD  264
#define F_ZB_LD  68
#define F_WHS_D   (256 * F_WHS_LD * 2)           // 36864 per dir
#define F_HS_OFF  (2 * F_WHS_D)                  // 73728
#define F_HS_D    (16 * F_HS_LD * 2)             // 8448 per dir
#define F_ZB_OFF  (F_HS_OFF + 2 * F_HS_D)        // 90624
#define F_ZB_D    (2 * 16 * F_ZB_LD * 4)         // 8704 per dir (two K-half planes)
#define F_SMEM    (F_ZB_OFF + 2 * F_ZB_D)        // 108032

__global__ __launch_bounds__(256, 1) void scan1_fused(
    const float* __restrict__ xw_f, const float* __restrict__ xw_b,
    const float* __restrict__ Wh_f, const float* __restrict__ Wh_b,
    const float* __restrict__ b_f,  const float* __restrict__ b_b,
    __nv_bfloat16* hb_base, unsigned* ctrs, float* x1out) {
    extern __shared__ char sm[];

    const int tid = threadIdx.x;
    const int w   = tid >> 5;
    const int bg  = blockIdx.x >> 4, ng = blockIdx.x & 15;
    const int r0  = bg * 8, hc0 = ng * 16;
    unsigned* ctr = ctrs + bg;

    // stage Wh slices (both dirs): Whs_d[k][c], c = gate*16+j -> col gate*256+hc0+j
    for (int i = tid; i < 2 * 256 * 64; i += 256) {
        int d  = i >> 14;
        int k  = (i >> 6) & 255, cc = i & 63;
        int gt = cc >> 4, j = cc & 15;
        const float* Whg = d ? Wh_b : Wh_f;
        ((__nv_bfloat16*)(sm + d * F_WHS_D))[k * F_WHS_LD + cc] =
            __float2bfloat16_rn(__ldg(&Whg[(size_t)k * 1024 + gt * 256 + hc0 + j]));
    }
    // zero hs (rows 8..15 stay zero forever)
    for (int i = tid; i < 2 * 16 * F_HS_LD; i += 256)
        ((__nv_bfloat16*)(sm + F_HS_OFF))[i] = __float2bfloat16(0.f);

    // h-load role: row lrow (0..7), 16B per thread per dir
    const int lrow = tid >> 5;
    const int lcol = (tid & 31) * 8;
    // MMA role: warp w -> dir dw, K-half q, n-half nh (two 16-col accumulators)
    const int dw = w >> 2;
    const int q  = (w >> 1) & 1;
    const int n0 = (w & 1) * 32;
    // gate role: dir dg = tid>>7, row gr, h-col gj
    const int dg = tid >> 7;
    const int gr = (tid >> 4) & 7, gj = tid & 15;
    const int xwbase = hc0 + gj;
    const float* xwg  = dg ? xw_b : xw_f;
    const float* bias = dg ? b_b  : b_f;
    __nv_bfloat16* hbg = hb_base + (size_t)dg * 2 * (B_SZ * 256);
    const float bi  = __ldg(&bias[0 * 256 + xwbase]);
    const float bfv = __ldg(&bias[1 * 256 + xwbase]);
    const float bgv = __ldg(&bias[2 * 256 + xwbase]);
    const float bo  = __ldg(&bias[3 * 256 + xwbase]);
    float c_state = 0.0f;
    __syncthreads();

    // prefetch xw for step 0 (fwd: t=0, bwd: t=T-1)
    float xwi, xwf, xwg_, xwo;
    {
        int t0 = dg ? (T_SEQ - 1) : 0;
        const float* p = xwg + ((size_t)(r0 + gr) * T_SEQ + t0) * 1024 + xwbase;
        xwi = __ldcs(p); xwf = __ldcs(p + 256); xwg_ = __ldcs(p + 512); xwo = __ldcs(p + 768);
    }

    for (int s = 0; s < T_SEQ; s++) {
        if (s > 0) {
            // wait for all 16 group CTAs (both dirs published under one arrive)
            if (tid == 0) {
                const unsigned tgt = 16u * (unsigned)s;
                unsigned v;
                do {
                    asm volatile("ld.acquire.gpu.global.u32 %0, [%1];" : "=r"(v) : "l"(ctr) : "memory");
                } while (v < tgt);
            }
            __syncthreads();
            // load h(s) for both dirs into hs_d rows 0..7
            #pragma unroll
            for (int d = 0; d < 2; d++) {
                const __nv_bfloat16* hread = hb_base + (size_t)d * 2 * (B_SZ * 256)
                                           + (s & 1) * (B_SZ * 256) + (r0 + lrow) * 256 + lcol;
                uint4 hv = __ldcg((const uint4*)hread);
                *(uint4*)((__nv_bfloat16*)(sm + F_HS_OFF + d * F_HS_D) + lrow * F_HS_LD + lcol) = hv;
            }
            __syncthreads();
            // MMA: warp (dw, q, n0/n0+16); two independent 8-deep chains over 128 k
            {
                const __nv_bfloat16* hsd  = (const __nv_bfloat16*)(sm + F_HS_OFF + dw * F_HS_D);
                const __nv_bfloat16* whsd = (const __nv_bfloat16*)(sm + dw * F_WHS_D);
                wmma::fragment<wmma::accumulator, 16, 16, 16, float> acc0, acc1;
                wmma::fill_fragment(acc0, 0.0f);
                wmma::fill_fragment(acc1, 0.0f);
                const int kbase = q * 128;
                #pragma unroll
                for (int kt = 0; kt < 8; kt++) {
                    wmma::fragment<wmma::matrix_a, 16, 16, 16, __nv_bfloat16, wmma::row_major> a;
                    wmma::fragment<wmma::matrix_b, 16, 16, 16, __nv_bfloat16, wmma::row_major> b0, b1;
                    const int kk = kbase + kt * 16;
                    wmma::load_matrix_sync(a, hsd + kk, F_HS_LD);
                    wmma::load_matrix_sync(b0, whsd + kk * F_WHS_LD + n0, F_WHS_LD);
                    wmma::load_matrix_sync(b1, whsd + kk * F_WHS_LD + n0 + 16, F_WHS_LD);
                    wmma::mma_sync(acc0, a, b0, acc0);
                    wmma::mma_sync(acc1, a, b1, acc1);
                }
                float* plane = (float*)(sm + F_ZB_OFF + dw * F_ZB_D) + q * (16 * F_ZB_LD);
                wmma::store_matrix_sync(plane + n0, acc0, F_ZB_LD, wmma::mem_row_major);
                wmma::store_matrix_sync(plane + n0 + 16, acc1, F_ZB_LD, wmma::mem_row_major);
            }
        }
        __syncthreads();

        // gates: all 256 threads; thread -> (dir dg, row r0+gr, h-col hc0+gj)
        {
            const int t_in = dg ? (T_SEQ - 1 - s) : s;
            float zi = bi + xwi, zf = bfv + xwf, zg = bgv + xwg_, zo = bo + xwo;
            if (s > 0) {
                const float* z0 = (const float*)(sm + F_ZB_OFF + dg * F_ZB_D) + gr * F_ZB_LD;
                const float* z1 = z0 + 16 * F_ZB_LD;
                zi += z0[gj]      + z1[gj];
                zf += z0[16 + gj] + z1[16 + gj];
                zg += z0[32 + gj] + z1[32 + gj];
                zo += z0[48 + gj] + z1[48 + gj];
            }
            c_state = sig_ap(zf) * c_state + sig_ap(zi) * tanh_ap(zg);
            float hval = sig_ap(zo) * tanh_ap(c_state);

            // publish h(s+1) FIRST
            if (s < T_SEQ - 1) {
                __nv_bfloat16 hv = __float2bfloat16_rn(hval);
                __stcg((__nv_bfloat16*)(hbg + ((s + 1) & 1) * (B_SZ * 256) + (r0 + gr) * 256 + hc0 + gj), hv);
            }
            __stcg(x1out + ((size_t)(r0 + gr) * T_SEQ + t_in) * 512 + dg * 256 + hc0 + gj, hval);
            if (s < T_SEQ - 1) {
                int tn = dg ? (T_SEQ - 2 - s) : (s + 1);
                const float* p = xwg + ((size_t)(r0 + gr) * T_SEQ + tn) * 1024 + xwbase;
                xwi = __ldcs(p); xwf = __ldcs(p + 256); xwg_ = __ldcs(p + 512); xwo = __ldcs(p + 768);
            }
        }
        if (s == T_SEQ - 1) break;

        __syncthreads();   // all h stores issued before tid0's release
        if (tid == 0)
            asm volatile("red.release.gpu.global.add.u32 [%0], %1;" :: "l"(ctr), "r"(1u) : "memory");
    }
}

// ---------------- layer-2 scan (R11 kernel; single dir) ----------------
#define WHS_LD 72
#define HS_LD  264
#define ZB_LD  68
#define WHS_BYTES (256 * WHS_LD * 2)          // 36864
#define HS_OFF    WHS_BYTES
#define HS_BYTES  (16 * HS_LD * 2)            // 8448
#define ZB_OFF    (HS_OFF + HS_BYTES)         // 45312
#define ZB_BYTES  (2 * 16 * ZB_LD * 4)        // 8704
#define SCAN_SMEM (ZB_OFF + ZB_BYTES)         // 54016

__global__ __launch_bounds__(256, 2) void scan_kernel(
    const float* __restrict__ xw_f,
    const float* __restrict__ Wh_f,
    const float* __restrict__ b_f,
    __nv_bfloat16* hb, unsigned* ctrs,
    float* h2out) {
    extern __shared__ char sm[];
    __nv_bfloat16* Whs = (__nv_bfloat16*)sm;
    __nv_bfloat16* hs  = (__nv_bfloat16*)(sm + HS_OFF);
    float*         zb  = (float*)(sm + ZB_OFF);

    const int tid = threadIdx.x;
    const int w   = tid >> 5;
    const int sub = blockIdx.x & 127;
    const int bg  = sub >> 4, ng = sub & 15;
    const int r0  = bg * 8, hc0 = ng * 16;

    const float* xw   = xw_f;
    const float* Whg  = Wh_f;
    const float* bias = b_f;
    unsigned* ctr = ctrs + bg;

    for (int i = tid; i < 16 * HS_LD; i += 256) hs[i] = __float2bfloat16(0.f);
    for (int i = tid; i < 256 * 64; i += 256) {
        int k = i >> 6, cc = i & 63;
        int gt = cc >> 4, j = cc & 15;
        Whs[k * WHS_LD + cc] =
            __float2bfloat16_rn(__ldg(&Whg[(size_t)k * 1024 + gt * 256 + hc0 + j]));
    }

    const int lrow = tid >> 5;
    const int lcol = (tid & 31) * 8;
    const int q  = w >> 2;
    const int n0 = (w & 3) * 16;
    const int gr = tid >> 4, gj = tid & 15;
    const int xwbase = hc0 + gj;
    float bi = 0.f, bfv = 0.f, bgv = 0.f, bo = 0.f;
    if (tid < 128) {
        bi  = __ldg(&bias[0 * 256 + xwbase]);
        bfv = __ldg(&bias[1 * 256 + xwbase]);
        bgv = __ldg(&bias[2 * 256 + xwbase]);
        bo  = __ldg(&bias[3 * 256 + xwbase]);
    }
    float c_state = 0.0f;
    __syncthreads();

    float xwi = 0.f, xwf = 0.f, xwg = 0.f, xwo = 0.f;
    if (tid < 128) {
        const float* p = xw + ((size_t)(r0 + gr) * T_SEQ + 0) * 1024 + xwbase;
        xwi = __ldcs(p); xwf = __ldcs(p + 256); xwg = __ldcs(p + 512); xwo = __ldcs(p + 768);
    }

    for (int s = 0; s < T_SEQ; s++) {
        if (s > 0) {
            if (tid == 0) {
                const unsigned tgt = 16u * (unsigned)s;
                unsigned v;
                do {
                    asm volatile("ld.acquire.gpu.global.u32 %0, [%1];" : "=r"(v) : "l"(ctr) : "memory");
                } while (v < tgt);
            }
            __syncthreads();
            {
                const __nv_bfloat16* hread = hb + (s & 1) * (B_SZ * 256) + (r0 + lrow) * 256 + lcol;
                uint4 hv = __ldcg((const uint4*)hread);
                *(uint4*)(hs + lrow * HS_LD + lcol) = hv;
            }
            __syncthreads();
            {
                wmma::fragment<wmma::accumulator, 16, 16, 16, float> acc;
                wmma::fill_fragment(acc, 0.0f);
                const int kbase = q * 128;
                #pragma unroll
                for (int kt = 0; kt < 8; kt++) {
                    wmma::fragment<wmma::matrix_a, 16, 16, 16, __nv_bfloat16, wmma::row_major> a;
                    wmma::fragment<wmma::matrix_b, 16, 16, 16, __nv_bfloat16, wmma::row_major> b;
                    const int kk = kbase + kt * 16;
                    wmma::load_matrix_sync(a, hs + kk, HS_LD);
                    wmma::load_matrix_sync(b, Whs + kk * WHS_LD + n0, WHS_LD);
                    wmma::mma_sync(acc, a, b, acc);
                }
                wmma::store_matrix_sync(zb + q * (16 * ZB_LD) + n0, acc, ZB_LD, wmma::mem_row_major);
            }
        }
        __syncthreads();

        if (tid < 128) {
            float zi = bi + xwi, zf = bfv + xwf, zg = bgv + xwg, zo = bo + xwo;
            if (s > 0) {
                const float* z0 = zb + gr * ZB_LD;
                const float* z1 = z0 + 16 * ZB_LD;
                zi += z0[gj]      + z1[gj];
                zf += z0[16 + gj] + z1[16 + gj];
                zg += z0[32 + gj] + z1[32 + gj];
                zo += z0[48 + gj] + z1[48 + gj];
            }
            c_state = sig_ap(zf) * c_state + sig_ap(zi) * tanh_ap(zg);
            float hval = sig_ap(zo) * tanh_ap(c_state);

            if (s < T_SEQ - 1) {
                __nv_bfloat16 hv = __float2bfloat16_rn(hval);
                __stcg((__nv_bfloat16*)(hb + ((s + 1) & 1) * (B_SZ * 256) + (r0 + gr) * 256 + hc0 + gj), hv);
                const float* p = xw + ((size_t)(r0 + gr) * T_SEQ + (s + 1)) * 1024 + xwbase;
                xwi = __ldcs(p); xwf = __ldcs(p + 256); xwg = __ldcs(p + 512); xwo = __ldcs(p + 768);
            } else {
                h2out[(r0 + gr) * 256 + hc0 + gj] = hval;
            }
        }
        if (s == T_SEQ - 1) break;

        __syncthreads();
        if (tid == 0)
            asm volatile("red.release.gpu.global.add.u32 [%0], %1;" :: "l"(ctr), "r"(1u) : "memory");
    }
}

// ---------------- head: layer-2 bwd single step + final dot + sigmoid ----------------
__global__ __launch_bounds__(256) void head_kernel(const float* __restrict__ Wi,
                                                   const float* __restrict__ b2,
                                                   const float* __restrict__ Wd,
                                                   const float* __restrict__ bd,
                                                   float* __restrict__ out) {
    __shared__ float xr[512];
    __shared__ float z[1024];
    __shared__ float red[8];
    const int b = blockIdx.x, tid = threadIdx.x;
    const float* xrow = g_x1 + ((size_t)b * T_SEQ + (T_SEQ - 1)) * 512;
    xr[tid] = xrow[tid];
    xr[tid + 256] = xrow[tid + 256];
    __syncthreads();
    const int c0 = tid * 4;
    float4 acc = *(const float4*)(b2 + c0);
    for (int k = 0; k < 512; k++) {
        float xv = xr[k];
        float4 wv = __ldg((const float4*)(Wi + (size_t)k * 1024 + c0));
        acc.x = fmaf(xv, wv.x, acc.x);
        acc.y = fmaf(xv, wv.y, acc.y);
        acc.z = fmaf(xv, wv.z, acc.z);
        acc.w = fmaf(xv, wv.w, acc.w);
    }
    *(float4*)(z + c0) = acc;
    __syncthreads();
    float zi = z[tid], zg = z[512 + tid], zo = z[768 + tid];
    float cst = sigf(zi) * tanhf(zg);           // c0 = 0 so forget term vanishes
    float h2b = sigf(zo) * tanhf(cst);
    float pl = g_h2f[b * 256 + tid] * __ldg(&Wd[tid]) + h2b * __ldg(&Wd[256 + tid]);
    #pragma unroll
    for (int off = 16; off; off >>= 1) pl += __shfl_down_sync(0xffffffffu, pl, off);
    if ((tid & 31) == 0) red[tid >> 5] = pl;
    __syncthreads();
    if (tid == 0) {
        float ssum = 0.f;
        #pragma unroll
        for (int q = 0; q < 8; q++) ssum += red[q];
        out[b] = sigf(ssum + bd[0]);
    }
}

// ---------------- launch ----------------
extern "C" void kernel_launch(void* const* d_in, const int* in_sizes, int n_in,
                              void* d_out, int out_size) {
    const int*   tokens = (const int*)  d_in[0];
    const float* embed  = (const float*)d_in[1];
    const float* fw1_Wi = (const float*)d_in[2];
    const float* fw1_Wh = (const float*)d_in[3];
    const float* fw1_b  = (const float*)d_in[4];
    const float* bw1_Wi = (const float*)d_in[5];
    const float* bw1_Wh = (const float*)d_in[6];
    const float* bw1_b  = (const float*)d_in[7];
    const float* fw2_Wi = (const float*)d_in[8];
    const float* fw2_Wh = (const float*)d_in[9];
    const float* fw2_b  = (const float*)d_in[10];
    const float* bw2_Wi = (const float*)d_in[11];
    const float* bw2_b  = (const float*)d_in[13];
    const float* Wd     = (const float*)d_in[14];
    const float* bd     = (const float*)d_in[15];
    float* out = (float*)d_out;

    float *px, *pxw1f, *pxw1b, *pxw2, *px1, *ph2f;
    __nv_bfloat16* phb;
    unsigned* pctrs;
    cudaGetSymbolAddress((void**)&px,    g_x);
    cudaGetSymbolAddress((void**)&pxw1f, g_xw1f);
    cudaGetSymbolAddress((void**)&pxw1b, g_xw1b);
    cudaGetSymbolAddress((void**)&pxw2,  g_xw2);
    cudaGetSymbolAddress((void**)&px1,   g_x1);
    cudaGetSymbolAddress((void**)&ph2f,  g_h2f);
    cudaGetSymbolAddress((void**)&phb,   g_hb);
    cudaGetSymbolAddress((void**)&pctrs, g_ctrs);

    cudaFuncSetAttribute(scan1_fused, cudaFuncAttributeMaxDynamicSharedMemorySize, F_SMEM);
    cudaFuncSetAttribute(scan_kernel, cudaFuncAttributeMaxDynamicSharedMemorySize, SCAN_SMEM);

    init_kernel<<<1, 32>>>();
    gather_kernel<<<16384, 256>>>(tokens, embed);
    gemm_bf16<<<dim3(8, 512), 256>>>(px, fw1_Wi, pxw1f, 1024, 256);
    gemm_bf16<<<dim3(8, 512), 256>>>(px, bw1_Wi, pxw1b, 1024, 256);
    scan1_fused<<<128, 256, F_SMEM>>>(pxw1f, pxw1b, fw1_Wh, bw1_Wh, fw1_b, bw1_b,
                                      phb, pctrs, px1);
    gemm_bf16<<<dim3(8, 512), 256>>>(px1, fw2_Wi, pxw2, 1024, 512);
    scan_kernel<<<128, 256, SCAN_SMEM>>>(pxw2, fw2_Wh, fw2_b,
                                         phb + (size_t)2 * 2 * (B_SZ * 256), pctrs + 16,
                                         ph2f);
    head_kernel<<<64, 256>>>(bw2_Wi, bw2_b, Wd, bd, out);
}

// round 13
// speedup vs baseline: 1.0275x; 1.0275x over previous
#include <cuda_runtime.h>
#include <cuda_bf16.h>
#include <mma.h>
#include <cstdint>
#include <cstddef>

using namespace nvcuda;

#define T_SEQ 1024
#define B_SZ  64
// E = 256, H = 256, 4H = 1024

// ---------------- device-global scratch (no allocations) ----------------
__device__ float g_x   [(size_t)B_SZ * T_SEQ * 256];   // gathered embeddings
__device__ float g_xw1f[(size_t)B_SZ * T_SEQ * 1024];  // x @ fw1_Wi
__device__ float g_xw1b[(size_t)B_SZ * T_SEQ * 1024];  // x @ bw1_Wi
__device__ float g_xw2 [(size_t)B_SZ * T_SEQ * 1024];  // x1 @ fw2_Wi
__device__ float g_x1  [(size_t)B_SZ * T_SEQ * 512];   // layer-1 output [fwd|bwd]
__device__ float g_h2f [B_SZ * 256];                   // layer-2 fwd final h
__device__ __nv_bfloat16 g_hb[3][2][B_SZ * 256];       // h double buffers (l1f, l1b, l2)
__device__ unsigned g_ctrs[32];                        // group barrier counters

// ---------------- helpers ----------------
__device__ __forceinline__ float tanh_ap(float x) {
    float y;
    asm("tanh.approx.f32 %0, %1;" : "=f"(y) : "f"(x));
    return y;
}
__device__ __forceinline__ float sig_ap(float x) {
    return fmaf(tanh_ap(0.5f * x), 0.5f, 0.5f);
}
__device__ __forceinline__ float sigf(float x) {
    return __fdividef(1.0f, 1.0f + __expf(-x));
}

// ---------------- init: zero barrier counters (every replay) ----------------
__global__ void init_kernel() {
    int i = threadIdx.x;
    if (i < 32) g_ctrs[i] = 0u;
}

// ---------------- embedding gather ----------------
__global__ void gather_kernel(const int* __restrict__ tok, const float* __restrict__ emb) {
    size_t idx = (size_t)blockIdx.x * blockDim.x + threadIdx.x;  // 65536*64 float4
    int row = (int)(idx >> 6);
    int f   = (int)(idx & 63);
    int t   = __ldg(&tok[row]);
    ((float4*)g_x)[idx] = __ldg(&((const float4*)emb)[(size_t)t * 64 + f]);
}

// ---------------- bf16 WMMA GEMM, double-buffered: C[M,N] = A[M,K] @ B[K,N] ----------------
#define GLDA 40
#define GLDB 136
__global__ __launch_bounds__(256, 2) void gemm_bf16(const float* __restrict__ A,
                                                    const float* __restrict__ B,
                                                    float* __restrict__ C,
                                                    int N, int K) {
    __shared__ __nv_bfloat16 As[2][128 * GLDA];
    __shared__ __nv_bfloat16 Bs[2][32 * GLDB];
    const int tid = threadIdx.x;
    const int w   = tid >> 5;
    const int m0  = blockIdx.y * 128;
    const int n0  = blockIdx.x * 128;
    const int wm0 = (w >> 2) * 64;
    const int wn0 = (w & 3) * 32;

    wmma::fragment<wmma::accumulator, 16, 16, 16, float> c[4][2];
    #pragma unroll
    for (int i = 0; i < 4; i++)
        #pragma unroll
        for (int j = 0; j < 2; j++) wmma::fill_fragment(c[i][j], 0.0f);

    float4 ra[4], rb[4];

    #pragma unroll
    for (int p = 0; p < 4; p++) {
        int idx = tid + p * 256;
        int row = idx >> 3, c4 = idx & 7;
        ra[p] = __ldg(&((const float4*)(A + (size_t)(m0 + row) * K))[c4]);
    }
    #pragma unroll
    for (int p = 0; p < 4; p++) {
        int idx = tid + p * 256;
        int row = idx >> 5, c4 = idx & 31;
        rb[p] = __ldg(&((const float4*)(B + (size_t)row * N + n0))[c4]);
    }
    #pragma unroll
    for (int p = 0; p < 4; p++) {
        int idx = tid + p * 256;
        int row = idx >> 3, c4 = idx & 7;
        __nv_bfloat162* dst = (__nv_bfloat162*)(&As[0][row * GLDA + c4 * 4]);
        dst[0] = __floats2bfloat162_rn(ra[p].x, ra[p].y);
        dst[1] = __floats2bfloat162_rn(ra[p].z, ra[p].w);
    }
    #pragma unroll
    for (int p = 0; p < 4; p++) {
        int idx = tid + p * 256;
        int row = idx >> 5, c4 = idx & 31;
        __nv_bfloat162* dst = (__nv_bfloat162*)(&Bs[0][row * GLDB + c4 * 4]);
        dst[0] = __floats2bfloat162_rn(rb[p].x, rb[p].y);
        dst[1] = __floats2bfloat162_rn(rb[p].z, rb[p].w);
    }
    __syncthreads();

    const int nkt = K >> 5;
    for (int kt = 0; kt < nkt; kt++) {
        const int cur = kt & 1;
        const bool more = (kt + 1 < nkt);
        if (more) {
            #pragma unroll
            for (int p = 0; p < 4; p++) {
                int idx = tid + p * 256;
                int row = idx >> 3, c4 = idx & 7;
                ra[p] = __ldg(&((const float4*)(A + (size_t)(m0 + row) * K + (kt + 1) * 32))[c4]);
            }
            #pragma unroll
            for (int p = 0; p < 4; p++) {
                int idx = tid + p * 256;
                int row = idx >> 5, c4 = idx & 31;
                rb[p] = __ldg(&((const float4*)(B + (size_t)((kt + 1) * 32 + row) * N + n0))[c4]);
            }
        }
        #pragma unroll
        for (int kk = 0; kk < 32; kk += 16) {
            wmma::fragment<wmma::matrix_a, 16, 16, 16, __nv_bfloat16, wmma::row_major> a[4];
            wmma::fragment<wmma::matrix_b, 16, 16, 16, __nv_bfloat16, wmma::row_major> b[2];
            #pragma unroll
            for (int i = 0; i < 4; i++)
                wmma::load_matrix_sync(a[i], &As[cur][(wm0 + i * 16) * GLDA + kk], GLDA);
            #pragma unroll
            for (int j = 0; j < 2; j++)
                wmma::load_matrix_sync(b[j], &Bs[cur][kk * GLDB + wn0 + j * 16], GLDB);
            #pragma unroll
            for (int i = 0; i < 4; i++)
                #pragma unroll
                for (int j = 0; j < 2; j++)
                    wmma::mma_sync(c[i][j], a[i], b[j], c[i][j]);
        }
        if (more) {
            const int nxt = cur ^ 1;
            #pragma unroll
            for (int p = 0; p < 4; p++) {
                int idx = tid + p * 256;
                int row = idx >> 3, c4 = idx & 7;
                __nv_bfloat162* dst = (__nv_bfloat162*)(&As[nxt][row * GLDA + c4 * 4]);
                dst[0] = __floats2bfloat162_rn(ra[p].x, ra[p].y);
                dst[1] = __floats2bfloat162_rn(ra[p].z, ra[p].w);
            }
            #pragma unroll
            for (int p = 0; p < 4; p++) {
                int idx = tid + p * 256;
                int row = idx >> 5, c4 = idx & 31;
                __nv_bfloat162* dst = (__nv_bfloat162*)(&Bs[nxt][row * GLDB + c4 * 4]);
                dst[0] = __floats2bfloat162_rn(rb[p].x, rb[p].y);
                dst[1] = __floats2bfloat162_rn(rb[p].z, rb[p].w);
            }
        }
        __syncthreads();
    }
    #pragma unroll
    for (int i = 0; i < 4; i++)
        #pragma unroll
        for (int j = 0; j < 2; j++)
            wmma::store_matrix_sync(C + (size_t)(m0 + wm0 + i * 16) * N + n0 + wn0 + j * 16,
                                    c[i][j], N, wmma::mem_row_major);
}

// ---------------- persistent LSTM scan (R11 topology + 2-ahead prefetch) ----------------
// Grid: nDir*128 CTAs, 256 threads. CTA (dir, bg, ng): batch rows bg*8..+8,
// h-cols ng*16..+16 (=> 64 local z-cols). Wh slice in SMEM. h exchanged via
// global bf16 double buffer + per-group (16 CTA) counter. xw prefetched 2 steps
// ahead (removes DRAM tail jitter from the barrier max-of-16). x1out stores
// happen AFTER the release so the release only drains the small h publish.
#define WHS_LD 72
#define HS_LD  264
#define ZB_LD  68
#define WHS_BYTES (256 * WHS_LD * 2)          // 36864
#define HS_OFF    WHS_BYTES
#define HS_BYTES  (16 * HS_LD * 2)            // 8448
#define ZB_OFF    (HS_OFF + HS_BYTES)         // 45312
#define ZB_BYTES  (2 * 16 * ZB_LD * 4)        // 8704 (two K-half planes)
#define SCAN_SMEM (ZB_OFF + ZB_BYTES)         // 54016

__global__ __launch_bounds__(256, 2) void scan_kernel(
    const float* __restrict__ xw_f, const float* __restrict__ xw_b,
    const float* __restrict__ Wh_f, const float* __restrict__ Wh_b,
    const float* __restrict__ b_f,  const float* __restrict__ b_b,
    __nv_bfloat16* hb_base, unsigned* ctrs,
    float* x1out, float* h2out) {
    extern __shared__ char sm[];
    __nv_bfloat16* Whs = (__nv_bfloat16*)sm;
    __nv_bfloat16* hs  = (__nv_bfloat16*)(sm + HS_OFF);
    float*         zb  = (float*)(sm + ZB_OFF);

    const int tid = threadIdx.x;
    const int w   = tid >> 5;
    const int dir = blockIdx.x >> 7;              // scan2 grid=128 -> always 0
    const int sub = blockIdx.x & 127;
    const int bg  = sub >> 4, ng = sub & 15;
    const int r0  = bg * 8, hc0 = ng * 16;

    const float* xw   = dir ? xw_b : xw_f;
    const float* Whg  = dir ? Wh_b : Wh_f;
    const float* bias = dir ? b_b  : b_f;
    __nv_bfloat16* hb = hb_base + (size_t)dir * 2 * (B_SZ * 256);
    unsigned* ctr = ctrs + dir * 8 + bg;

    // zero hs once (rows 8..15 stay zero forever -> M padded to 16)
    for (int i = tid; i < 16 * HS_LD; i += 256) hs[i] = __float2bfloat16(0.f);
    // stage Wh slice bf16: Whs[k][c], c = gate*16+j -> global col gate*256+hc0+j
    for (int i = tid; i < 256 * 64; i += 256) {
        int k = i >> 6, cc = i & 63;
        int gt = cc >> 4, j = cc & 15;
        Whs[k * WHS_LD + cc] =
            __float2bfloat16_rn(__ldg(&Whg[(size_t)k * 1024 + gt * 256 + hc0 + j]));
    }

    // h-load role: row lrow (0..7), 8 bf16 (16B) per thread
    const int lrow = tid >> 5;
    const int lcol = (tid & 31) * 8;
    // MMA role: K-half q, local col base n0
    const int q  = w >> 2;
    const int n0 = (w & 3) * 16;
    // gate role (tid < 128): row gr, h-col gj
    const int gr = tid >> 4, gj = tid & 15;
    const int xwbase = hc0 + gj;
    float bi = 0.f, bfv = 0.f, bgv = 0.f, bo = 0.f;
    if (tid < 128) {
        bi  = __ldg(&bias[0 * 256 + xwbase]);
        bfv = __ldg(&bias[1 * 256 + xwbase]);
        bgv = __ldg(&bias[2 * 256 + xwbase]);
        bo  = __ldg(&bias[3 * 256 + xwbase]);
    }
    float c_state = 0.0f;
    const float* xwrow = xw + (size_t)(r0 + gr) * T_SEQ * 1024 + xwbase;
    __syncthreads();

    // prefetch xw for steps 0 and 1 (2-deep register pipeline)
    float4 xv0 = make_float4(0.f, 0.f, 0.f, 0.f);
    float4 xv1 = make_float4(0.f, 0.f, 0.f, 0.f);
    if (tid < 128) {
        int ta = dir ? (T_SEQ - 1) : 0;
        int tb = dir ? (T_SEQ - 2) : 1;
        const float* pa = xwrow + (size_t)ta * 1024;
        const float* pb = xwrow + (size_t)tb * 1024;
        xv0.x = __ldcs(pa); xv0.y = __ldcs(pa + 256); xv0.z = __ldcs(pa + 512); xv0.w = __ldcs(pa + 768);
        xv1.x = __ldcs(pb); xv1.y = __ldcs(pb + 256); xv1.z = __ldcs(pb + 512); xv1.w = __ldcs(pb + 768);
    }

    // one scan step; consumes xc (xw for step s), refills it with step s+2
    auto do_step = [&](int s, float4& xc) -> bool {
        if (s > 0) {
            // wait for all 16 group CTAs to have published h(s)
            if (tid == 0) {
                const unsigned tgt = 16u * (unsigned)s;
                unsigned v;
                do {
                    asm volatile("ld.acquire.gpu.global.u32 %0, [%1];" : "=r"(v) : "l"(ctr) : "memory");
                } while (v < tgt);
            }
            __syncthreads();
            // load h(s) [8 rows x 256] bf16 from L2 into hs rows 0..7
            {
                const __nv_bfloat16* hread = hb + (s & 1) * (B_SZ * 256) + (r0 + lrow) * 256 + lcol;
                uint4 hv = __ldcg((const uint4*)hread);
                *(uint4*)(hs + lrow * HS_LD + lcol) = hv;
            }
            __syncthreads();
            // K-split MMA: warp (q, n0); 8-deep chain over its 128 k
            {
                wmma::fragment<wmma::accumulator, 16, 16, 16, float> acc;
                wmma::fill_fragment(acc, 0.0f);
                const int kbase = q * 128;
                #pragma unroll
                for (int kt = 0; kt < 8; kt++) {
                    wmma::fragment<wmma::matrix_a, 16, 16, 16, __nv_bfloat16, wmma::row_major> a;
                    wmma::fragment<wmma::matrix_b, 16, 16, 16, __nv_bfloat16, wmma::row_major> b;
                    const int kk = kbase + kt * 16;
                    wmma::load_matrix_sync(a, hs + kk, HS_LD);
                    wmma::load_matrix_sync(b, Whs + kk * WHS_LD + n0, WHS_LD);
                    wmma::mma_sync(acc, a, b, acc);
                }
                wmma::store_matrix_sync(zb + q * (16 * ZB_LD) + n0, acc, ZB_LD, wmma::mem_row_major);
            }
        }
        __syncthreads();

        const bool last = (s == T_SEQ - 1);
        float hval = 0.f;
        if (tid < 128) {
            float zi = bi + xc.x, zf = bfv + xc.y, zg = bgv + xc.z, zo = bo + xc.w;
            if (s > 0) {
                const float* z0 = zb + gr * ZB_LD;
                const float* z1 = z0 + 16 * ZB_LD;
                zi += z0[gj]      + z1[gj];
                zf += z0[16 + gj] + z1[16 + gj];
                zg += z0[32 + gj] + z1[32 + gj];
                zo += z0[48 + gj] + z1[48 + gj];
            }
            c_state = sig_ap(zf) * c_state + sig_ap(zi) * tanh_ap(zg);
            hval = sig_ap(zo) * tanh_ap(c_state);
            if (!last) {
                // publish h(s+1) — the ONLY store the release has to order
                __nv_bfloat16 hv = __float2bfloat16_rn(hval);
                __stcg((__nv_bfloat16*)(hb + ((s + 1) & 1) * (B_SZ * 256) + (r0 + gr) * 256 + hc0 + gj), hv);
            }
        }
        const int t_in = dir ? (T_SEQ - 1 - s) : s;
        if (last) {
            if (tid < 128) {
                if (x1out)
                    __stcg(x1out + ((size_t)(r0 + gr) * T_SEQ + t_in) * 512 + dir * 256 + hc0 + gj, hval);
                if (h2out)
                    h2out[(r0 + gr) * 256 + hc0 + gj] = hval;
            }
            return true;
        }
        __syncthreads();   // all h stores issued before tid0's release
        if (tid == 0)
            asm volatile("red.release.gpu.global.add.u32 [%0], %1;" :: "l"(ctr), "r"(1u) : "memory");
        // post-release: bulk output store + 2-ahead prefetch (off the release path)
        if (tid < 128) {
            if (x1out)
                __stcg(x1out + ((size_t)(r0 + gr) * T_SEQ + t_in) * 512 + dir * 256 + hc0 + gj, hval);
            if (s + 2 < T_SEQ) {
                int tn = dir ? (T_SEQ - 1 - (s + 2)) : (s + 2);
                const float* p = xwrow + (size_t)tn * 1024;
                xc.x = __ldcs(p); xc.y = __ldcs(p + 256); xc.z = __ldcs(p + 512); xc.w = __ldcs(p + 768);
            }
        }
        return false;
    };

    for (int s = 0; s < T_SEQ; s += 2) {
        if (do_step(s, xv0)) break;
        if (do_step(s + 1, xv1)) break;
    }
}

// ---------------- head: layer-2 bwd single step + final dot + sigmoid ----------------
__global__ __launch_bounds__(256) void head_kernel(const float* __restrict__ Wi,
                                                   const float* __restrict__ b2,
                                                   const float* __restrict__ Wd,
                                                   const float* __restrict__ bd,
                                                   float* __restrict__ out) {
    __shared__ float xr[512];
    __shared__ float z[1024];
    __shared__ float red[8];
    const int b = blockIdx.x, tid = threadIdx.x;
    const float* xrow = g_x1 + ((size_t)b * T_SEQ + (T_SEQ - 1)) * 512;
    xr[tid] = xrow[tid];
    xr[tid + 256] = xrow[tid + 256];
    __syncthreads();
    const int c0 = tid * 4;
    float4 acc = *(const float4*)(b2 + c0);
    for (int k = 0; k < 512; k++) {
        float xv = xr[k];
        float4 wv = __ldg((const float4*)(Wi + (size_t)k * 1024 + c0));
        acc.x = fmaf(xv, wv.x, acc.x);
        acc.y = fmaf(xv, wv.y, acc.y);
        acc.z = fmaf(xv, wv.z, acc.z);
        acc.w = fmaf(xv, wv.w, acc.w);
    }
    *(float4*)(z + c0) = acc;
    __syncthreads();
    float zi = z[tid], zg = z[512 + tid], zo = z[768 + tid];
    float cst = sigf(zi) * tanhf(zg);           // c0 = 0 so forget term vanishes
    float h2b = sigf(zo) * tanhf(cst);
    float pl = g_h2f[b * 256 + tid] * __ldg(&Wd[tid]) + h2b * __ldg(&Wd[256 + tid]);
    #pragma unroll
    for (int off = 16; off; off >>= 1) pl += __shfl_down_sync(0xffffffffu, pl, off);
    if ((tid & 31) == 0) red[tid >> 5] = pl;
    __syncthreads();
    if (tid == 0) {
        float ssum = 0.f;
        #pragma unroll
        for (int q = 0; q < 8; q++) ssum += red[q];
        out[b] = sigf(ssum + bd[0]);
    }
}

// ---------------- launch ----------------
extern "C" void kernel_launch(void* const* d_in, const int* in_sizes, int n_in,
                              void* d_out, int out_size) {
    const int*   tokens = (const int*)  d_in[0];
    const float* embed  = (const float*)d_in[1];
    const float* fw1_Wi = (const float*)d_in[2];
    const float* fw1_Wh = (const float*)d_in[3];
    const float* fw1_b  = (const float*)d_in[4];
    const float* bw1_Wi = (const float*)d_in[5];
    const float* bw1_Wh = (const float*)d_in[6];
    const float* bw1_b  = (const float*)d_in[7];
    const float* fw2_Wi = (const float*)d_in[8];
    const float* fw2_Wh = (const float*)d_in[9];
    const float* fw2_b  = (const float*)d_in[10];
    const float* bw2_Wi = (const float*)d_in[11];
    const float* bw2_b  = (const float*)d_in[13];
    const float* Wd     = (const float*)d_in[14];
    const float* bd     = (const float*)d_in[15];
    float* out = (float*)d_out;

    float *px, *pxw1f, *pxw1b, *pxw2, *px1, *ph2f;
    __nv_bfloat16* phb;
    unsigned* pctrs;
    cudaGetSymbolAddress((void**)&px,    g_x);
    cudaGetSymbolAddress((void**)&pxw1f, g_xw1f);
    cudaGetSymbolAddress((void**)&pxw1b, g_xw1b);
    cudaGetSymbolAddress((void**)&pxw2,  g_xw2);
    cudaGetSymbolAddress((void**)&px1,   g_x1);
    cudaGetSymbolAddress((void**)&ph2f,  g_h2f);
    cudaGetSymbolAddress((void**)&phb,   g_hb);
    cudaGetSymbolAddress((void**)&pctrs, g_ctrs);

    cudaFuncSetAttribute(scan_kernel, cudaFuncAttributeMaxDynamicSharedMemorySize, SCAN_SMEM);

    init_kernel<<<1, 32>>>();
    gather_kernel<<<16384, 256>>>(tokens, embed);
    gemm_bf16<<<dim3(8, 512), 256>>>(px, fw1_Wi, pxw1f, 1024, 256);
    gemm_bf16<<<dim3(8, 512), 256>>>(px, bw1_Wi, pxw1b, 1024, 256);
    scan_kernel<<<256, 256, SCAN_SMEM>>>(pxw1f, pxw1b, fw1_Wh, bw1_Wh, fw1_b, bw1_b,
                                         phb, pctrs, px1, nullptr);
    gemm_bf16<<<dim3(8, 512), 256>>>(px1, fw2_Wi, pxw2, 1024, 512);
    scan_kernel<<<128, 256, SCAN_SMEM>>>(pxw2, pxw2, fw2_Wh, fw2_Wh, fw2_b, fw2_b,
                                         phb + (size_t)2 * 2 * (B_SZ * 256), pctrs + 16,
                                         nullptr, ph2f);
    head_kernel<<<64, 256>>>(bw2_Wi, bw2_b, Wd, bd, out);
}